// round 4
// baseline (speedup 1.0000x reference)
#include <cuda_runtime.h>
#include <math.h>

#define N_NODES 40000
#define N_EDGES 640000
#define HID     128
#define NH      (N_NODES * HID)

typedef unsigned long long u64;

// ---------------- device scratch (no allocations allowed) ----------------
__device__ __align__(16) float g_xproj[NH];
__device__ __align__(16) float g_stateA[NH];
__device__ __align__(16) float g_stateB[NH];
__device__ __align__(16) float g_wt[HID * HID];
__device__ int   g_rowptr[N_NODES + 1];
__device__ int   g_cursor[N_NODES];
__device__ int   g_counts[N_NODES];
__device__ int   g_col[N_EDGES];
__device__ int   g_is64;

// ---------------- packed f32x2 helpers (B300 FFMA2 path) ----------------
__device__ __forceinline__ u64 pack_dup(float a) {
    u64 r; asm("mov.b64 %0, {%1,%1};" : "=l"(r) : "f"(a)); return r;
}
__device__ __forceinline__ void fma2(u64& d, u64 a, u64 b) {
    asm("fma.rn.f32x2 %0, %1, %2, %3;" : "=l"(d) : "l"(a), "l"(b), "l"(d));
}
__device__ __forceinline__ float2 unpack2(u64 v) {
    float2 f; asm("mov.b64 {%0,%1}, %2;" : "=f"(f.x), "=f"(f.y) : "l"(v)); return f;
}

// ---------------- edge dtype probe: int64 vs int32 ----------------
__global__ void detect_kernel(const void* ei) {
    if (threadIdx.x == 0 && blockIdx.x == 0) {
        const long long* p = (const long long*)ei;
        int ok64 = 1;
        for (int i = 0; i < 64; i++) {
            long long v = p[(i * 9973) % 640000];
            if (v < 0 || v >= N_NODES) { ok64 = 0; break; }
        }
        g_is64 = ok64;
    }
}

__device__ __forceinline__ int edge_val(const void* ei, int idx) {
    int v;
    if (g_is64) v = (int)((const long long*)ei)[idx];
    else        v = ((const int*)ei)[idx];
    return ((unsigned)v < N_NODES) ? v : 0;   // clamp: never trap
}

// ---------------- CSR build ----------------
__global__ void zero_counts_kernel() {
    for (int i = blockIdx.x * blockDim.x + threadIdx.x; i < N_NODES;
         i += gridDim.x * blockDim.x)
        g_counts[i] = 0;
}

__global__ void hist_kernel(const void* __restrict__ ei) {
    int e = blockIdx.x * blockDim.x + threadIdx.x;
    if (e < N_EDGES) {
        int dst = edge_val(ei, N_EDGES + e);
        atomicAdd(&g_counts[dst], 1);
    }
}

// fast single-block scan: 1024 threads x 40 contiguous elements + shuffle scans
__global__ void scan_kernel() {
    __shared__ int wsum[32];
    int t = threadIdx.x, lane = t & 31, wid = t >> 5;
    const int PER = 40;          // 1024*40 = 40960 >= N_NODES
    int base = t * PER;
    int s = 0;
    for (int j = 0; j < PER; j++) {
        int i = base + j;
        if (i < N_NODES) s += g_counts[i];
    }
    int v = s;
    for (int o = 1; o < 32; o <<= 1) {
        int n = __shfl_up_sync(0xffffffffu, v, o);
        if (lane >= o) v += n;
    }
    if (lane == 31) wsum[wid] = v;
    __syncthreads();
    if (wid == 0) {
        int w = wsum[lane];
        int vv = w;
        for (int o = 1; o < 32; o <<= 1) {
            int n = __shfl_up_sync(0xffffffffu, vv, o);
            if (lane >= o) vv += n;
        }
        wsum[lane] = vv - w;   // exclusive warp offsets
    }
    __syncthreads();
    int run = wsum[wid] + (v - s);   // exclusive prefix at this thread's chunk
    for (int j = 0; j < PER; j++) {
        int i = base + j;
        if (i < N_NODES) {
            int c = g_counts[i];
            g_cursor[i] = run;
            run += c;
            g_rowptr[i + 1] = run;
        }
    }
    if (t == 0) g_rowptr[0] = 0;
}

__global__ void fill_kernel(const void* __restrict__ ei) {
    int e = blockIdx.x * blockDim.x + threadIdx.x;
    if (e < N_EDGES) {
        int src = edge_val(ei, e);
        int dst = edge_val(ei, N_EDGES + e);
        int pos = atomicAdd(&g_cursor[dst], 1);
        if ((unsigned)pos < N_EDGES) g_col[pos] = src;
    }
}

// ---------------- transpose 128x128 into g_wt: wt[k][h] = w[h][k] ----------------
__global__ void transpose128_kernel(const float* __restrict__ w) {
    int idx = blockIdx.x * blockDim.x + threadIdx.x;
    if (idx < HID * HID) {
        int h = idx >> 7, k = idx & 127;
        g_wt[k * HID + h] = w[h * HID + k];
    }
}

// ---------------- first state update: stateA = tanh(xproj) ----------------
__global__ void tanh_kernel() {
    int i = blockIdx.x * blockDim.x + threadIdx.x;
    if (i < NH) g_stateA[i] = tanhf(g_xproj[i]);
}

// ---------------- shared GEMM body: dst[r][h] = f(bias + sum_k sA[r][k]*W[k][h]) ----
// 256 threads, 64 rows/block, thread tile 4 rows x 8 cols (4 f32x2 col-pairs).
// sA row-major [64][AP], W global [k][h] tiled by KT into sW.
#define GR 64
#define AP 132          // row pitch in floats (132*4 = 528 B, 16B-aligned, bank-safe)
#define KT 16

__device__ __forceinline__ void gemm_body(
    float* sA, float* sW, const float* __restrict__ W,
    float* __restrict__ dst, int row0, int use_bias, int do_tanh, int t)
{
    int tc = t & 15;    // cols tc*8 .. +7
    int tr = t >> 4;    // rows tr*4 .. +3

    u64 acc[4][4];
#pragma unroll
    for (int i = 0; i < 4; i++)
#pragma unroll
        for (int j = 0; j < 4; j++) acc[i][j] = 0ull;

    for (int k0 = 0; k0 < HID; k0 += KT) {
        // load W tile: KT*128 floats = 512 float4 (2 per thread)
        {
            const float4* Wv = (const float4*)(W + k0 * HID);
            float4* sWv = (float4*)sW;
            sWv[t]       = Wv[t];
            sWv[t + 256] = Wv[t + 256];
        }
        __syncthreads();
#pragma unroll
        for (int kk = 0; kk < KT; kk++) {
            ulonglong2 w01 = *(const ulonglong2*)&sW[kk * HID + tc * 8];
            ulonglong2 w23 = *(const ulonglong2*)&sW[kk * HID + tc * 8 + 4];
#pragma unroll
            for (int i = 0; i < 4; i++) {
                u64 a = pack_dup(sA[(tr * 4 + i) * AP + k0 + kk]);
                fma2(acc[i][0], a, w01.x);
                fma2(acc[i][1], a, w01.y);
                fma2(acc[i][2], a, w23.x);
                fma2(acc[i][3], a, w23.y);
            }
        }
        __syncthreads();
    }

#pragma unroll
    for (int i = 0; i < 4; i++) {
        int r = row0 + tr * 4 + i;
        float v[8];
#pragma unroll
        for (int j = 0; j < 4; j++) {
            float2 p = unpack2(acc[i][j]);
            v[2 * j] = p.x; v[2 * j + 1] = p.y;
        }
        if (use_bias) {
            float4 b0 = *(const float4*)&g_xproj[r * HID + tc * 8];
            float4 b1 = *(const float4*)&g_xproj[r * HID + tc * 8 + 4];
            v[0] += b0.x; v[1] += b0.y; v[2] += b0.z; v[3] += b0.w;
            v[4] += b1.x; v[5] += b1.y; v[6] += b1.z; v[7] += b1.w;
        }
        if (do_tanh) {
#pragma unroll
            for (int j = 0; j < 8; j++) v[j] = tanhf(v[j]);
        }
        *(float4*)&dst[r * HID + tc * 8]     = make_float4(v[0], v[1], v[2], v[3]);
        *(float4*)&dst[r * HID + tc * 8 + 4] = make_float4(v[4], v[5], v[6], v[7]);
    }
}

// ---------------- projection GEMM: xproj = A @ g_wt  (A = x ext or stateA) ------
__global__ void __launch_bounds__(256) proj_kernel(const float* __restrict__ Aext,
                                                   int a_sel)
{
    __shared__ float sA[GR * AP];
    __shared__ float sW[KT * HID];
    const float* A = a_sel ? g_stateA : Aext;
    int t = threadIdx.x;
    int row0 = blockIdx.x * GR;
#pragma unroll
    for (int j = 0; j < 8; j++) {
        int idx = t + j * 256;       // 0..2047
        int r   = idx >> 5;          // 0..63
        int k4  = idx & 31;          // 0..31
        float4 vv = *(const float4*)&A[(row0 + r) * HID + k4 * 4];
        *(float4*)&sA[r * AP + k4 * 4] = vv;
    }
    gemm_body(sA, sW, g_wt, g_xproj, row0, 0, 0, t);
}

// ---------------- fused aggregate + recurrent GEMM + tanh ----------------
// src_sel: 0=stateA 1=stateB ; dst_sel: 0=stateA 1=stateB 2=out_ext
__global__ void __launch_bounds__(256) fused_kernel(const float* __restrict__ W,
                                                    int src_sel, int dst_sel,
                                                    float* __restrict__ out_ext)
{
    __shared__ float sA[GR * AP];
    __shared__ float sW[KT * HID];
    const float* state = src_sel ? g_stateB : g_stateA;
    float* dst = (dst_sel == 2) ? out_ext : (dst_sel ? g_stateB : g_stateA);

    int t = threadIdx.x;
    int row0 = blockIdx.x * GR;
    int wrp = t >> 5, lane = t & 31;
    const float4* st = (const float4*)state;

    // gather: each warp aggregates 8 nodes, float4 per lane (h = lane*4..+3)
#pragma unroll
    for (int q = 0; q < 8; q++) {
        int r = wrp * 8 + q;
        int node = row0 + r;
        int s = g_rowptr[node];
        int e = g_rowptr[node + 1];
        float4 acc = make_float4(0.f, 0.f, 0.f, 0.f);
        for (int i = s; i < e; i++) {
            float4 v = st[g_col[i] * 32 + lane];
            acc.x += v.x; acc.y += v.y; acc.z += v.z; acc.w += v.w;
        }
        *(float4*)&sA[r * AP + lane * 4] = acc;
    }
    // gemm_body's first __syncthreads covers the sA writes
    gemm_body(sA, sW, W, dst, row0, 1, 1, t);
}

// ---------------- host orchestration ----------------
extern "C" void kernel_launch(void* const* d_in, const int* in_sizes, int n_in,
                              void* d_out, int out_size)
{
    // Discover inputs by element count (robust to ordering):
    const void* ei = nullptr;
    const float* x = nullptr;
    const float* w[4] = {nullptr, nullptr, nullptr, nullptr};
    int wn = 0;
    for (int i = 0; i < n_in; i++) {
        if (in_sizes[i] == 2 * N_EDGES)      ei = d_in[i];
        else if (in_sizes[i] == NH)          x  = (const float*)d_in[i];
        else if (in_sizes[i] == HID * HID && wn < 4) w[wn++] = (const float*)d_in[i];
    }
    const float* w_in0  = w[0];
    const float* w_rec0 = w[1];
    const float* w_in1  = w[2];
    const float* w_rec1 = w[3];
    float* out = (float*)d_out;

    // Build dst-major CSR once per launch
    detect_kernel<<<1, 32>>>(ei);
    zero_counts_kernel<<<40, 1024>>>();
    hist_kernel<<<(N_EDGES + 255) / 256, 256>>>(ei);
    scan_kernel<<<1, 1024>>>();
    fill_kernel<<<(N_EDGES + 255) / 256, 256>>>(ei);

    const int BLOCKS = N_NODES / GR;             // 625
    const int TANH_BLOCKS = (NH + 255) / 256;

    for (int layer = 0; layer < 2; layer++) {
        const float* win  = layer ? w_in1  : w_in0;
        const float* wrec = layer ? w_rec1 : w_rec0;

        // xproj = input @ win^T
        transpose128_kernel<<<64, 256>>>(win);
        proj_kernel<<<BLOCKS, 256>>>(layer ? nullptr : x, layer ? 1 : 0);

        // state update #1 (initial state zero): stateA = tanh(xproj)
        tanh_kernel<<<TANH_BLOCKS, 256>>>();

        // 8 more updates: state = tanh(xproj + aggr(state) @ wrec)
        // ping-pong A->B->A->... (ends back in A after 8 iterations)
        for (int it = 0; it < 8; it++) {
            int src = it & 1;            // 0=A,1=B
            int last = (layer == 1 && it == 7);
            int dst = last ? 2 : (1 - src);
            fused_kernel<<<BLOCKS, 256>>>(wrec, src, dst, last ? out : nullptr);
        }
    }
}